// round 14
// baseline (speedup 1.0000x reference)
#include <cuda_runtime.h>
#include <cuda_fp16.h>
#include <cstdint>

// Problem constants
#define Mm   1024
#define Nv   2048
#define DVd  3
#define DCd  6
#define Bb   128
#define Tt   5
#define CIN  48
#define VIN  25
#define HC   192
#define HV   100

// ---------------------------------------------------------------------------
// Device-global scratch
// ---------------------------------------------------------------------------
__device__ float g_chk_in[Mm * CIN * Bb];   // [m][c][b]
__device__ float g_var_x [Nv * VIN * Bb];   // [n][c][b], c=24 -> prior
__device__ float g_sgn   [Mm * Bb];         // [m][b] syndrome signs

// Fragment-packed fp16 weights, hi+lo fused per uint4 {bh0,bh1,bl0,bl1}.
// index: ((group*KT + kt)*NT + nt)*32 + lane
__device__ uint4 g_c1[Mm * 3 * 24 * 32];    // chk W1 48x192
__device__ uint4 g_c2[Mm * 12 * 6 * 32];    // chk W2 192x48
__device__ uint4 g_v1[Nv * 2 * 13 * 32];    // var W1 32x104 (padded)
__device__ uint4 g_v2[Nv * 7 * 4  * 32];    // var W2 112x32 (padded)

// Fast gelu: Phi via A&S 7.1.26 erf approx (|err| <= 1.5e-7), ~14 ops.
__device__ __forceinline__ float gelu_fast(float v) {
    float z = 0.70710678118654752f * v;
    float a = fabsf(z);
    float t = __fdividef(1.0f, fmaf(0.3275911f, a, 1.0f));
    float p = fmaf(1.061405429f, t, -1.453152027f);
    p = fmaf(p, t, 1.421413741f);
    p = fmaf(p, t, -0.284496736f);
    p = fmaf(p, t, 0.254829592f);
    p = p * t;
    float e = __expf(-a * a);
    float erf_a = fmaf(-p, e, 1.0f);
    float ph = (z >= 0.f) ? fmaf(0.5f, erf_a, 0.5f)
                          : fmaf(-0.5f, erf_a, 0.5f);
    return v * ph;
}

__device__ __forceinline__ uint32_t smem_u32(const void* p) {
    uint32_t a;
    asm("{ .reg .u64 t; cvta.to.shared.u64 t, %1; cvt.u32.u64 %0, t; }" : "=r"(a) : "l"(p));
    return a;
}

// pack two floats into fp16x2 (lo -> low half)
__device__ __forceinline__ uint32_t pkh(float lo, float hi) {
    __half2 h = __floats2half2_rn(lo, hi);
    return *reinterpret_cast<uint32_t*>(&h);
}
__device__ __forceinline__ void hl2(float a, float b, uint32_t& H, uint32_t& L) {
    float ra = __half2float(__float2half_rn(a));
    float rb = __half2float(__float2half_rn(b));
    H = pkh(a, b);
    L = pkh(a - ra, b - rb);
}

// D += A * B  (m16n8k16 fp16->fp32)
__device__ __forceinline__ void mma16816(float* c, const uint32_t* a,
                                         uint32_t b0, uint32_t b1) {
    asm volatile(
        "mma.sync.aligned.m16n8k16.row.col.f32.f16.f16.f32 "
        "{%0,%1,%2,%3}, {%4,%5,%6,%7}, {%8,%9}, {%0,%1,%2,%3};"
        : "+f"(c[0]), "+f"(c[1]), "+f"(c[2]), "+f"(c[3])
        : "r"(a[0]), "r"(a[1]), "r"(a[2]), "r"(a[3]), "r"(b0), "r"(b1));
}
__device__ __forceinline__ void ldsm4(uint32_t* r, uint32_t saddr) {
    asm volatile("ldmatrix.sync.aligned.m8n8.x4.shared.b16 {%0,%1,%2,%3}, [%4];"
        : "=r"(r[0]), "=r"(r[1]), "=r"(r[2]), "=r"(r[3]) : "r"(saddr));
}

// ---------------------------------------------------------------------------
// Init kernels
// ---------------------------------------------------------------------------
__global__ void init_chk(const float* __restrict__ prior,
                         const int*   __restrict__ chk_nbrs) {
    int i = blockIdx.x * 256 + threadIdx.x;
    if (i >= Mm * CIN * Bb) return;
    int c = (i >> 7) % CIN;
    float v = 0.0f;
    if ((c & 7) == 0) {
        int m = i / (CIN * Bb);
        v = prior[chk_nbrs[m * DCd + (c >> 3)]];
    }
    g_chk_in[i] = v;
}
__global__ void init_var(const float* __restrict__ prior) {
    int i = blockIdx.x * 256 + threadIdx.x;
    if (i >= Nv * Bb) return;
    int n = i >> 7, b = i & 127;
    g_var_x[(size_t)n * (VIN * Bb) + 24 * Bb + b] = prior[n];
}
__global__ void init_sgn(const int* __restrict__ synd) {
    int i = blockIdx.x * 256 + threadIdx.x;      // m*128 + b
    if (i >= Mm * Bb) return;
    int mi = i >> 7, b = i & 127;
    g_sgn[i] = 1.0f - 2.0f * (float)synd[b * Mm + mi];
}

// ---------------------------------------------------------------------------
// Prep kernels: pack weights into mma B-fragment order, fp16 hi/lo fused.
// B frag (kt,nt,lane): k0 = kt*16 + (l%4)*2, n = nt*8 + l/4
//   b0 = {B[k0][n], B[k0+1][n]},  b1 = {B[k0+8][n], B[k0+9][n]}
// ---------------------------------------------------------------------------
__device__ __forceinline__ uint4 pack4(float v0, float v1, float v2, float v3) {
    uint32_t h0, l0, h1, l1;
    hl2(v0, v1, h0, l0);
    hl2(v2, v3, h1, l1);
    return make_uint4(h0, h1, l0, l1);
}

__global__ void prep_chk_frag(const float* __restrict__ w1,
                              const float* __restrict__ w2) {
    int m = blockIdx.x;
    extern __shared__ float ps[];            // 9216 + 9216
    float* s1 = ps;
    float* s2 = ps + 9216;
    {
        const float4* a = (const float4*)(w1 + (size_t)m * 9216);
        const float4* b = (const float4*)(w2 + (size_t)m * 9216);
        float4* d1 = (float4*)s1;
        float4* d2 = (float4*)s2;
        for (int k = threadIdx.x; k < 2304; k += 256) { d1[k] = a[k]; d2[k] = b[k]; }
    }
    __syncthreads();
    for (int t = threadIdx.x; t < 3 * 24 * 32; t += 256) {
        int kt = t / (24 * 32), nt = (t >> 5) % 24, l = t & 31;
        int k0 = kt * 16 + (l & 3) * 2, n = nt * 8 + (l >> 2);
        g_c1[((size_t)(m * 3 + kt) * 24 + nt) * 32 + l] =
            pack4(s1[k0 * HC + n], s1[(k0 + 1) * HC + n],
                  s1[(k0 + 8) * HC + n], s1[(k0 + 9) * HC + n]);
    }
    for (int t = threadIdx.x; t < 12 * 6 * 32; t += 256) {
        int kt = t / (6 * 32), nt = (t >> 5) % 6, l = t & 31;
        int k0 = kt * 16 + (l & 3) * 2, n = nt * 8 + (l >> 2);
        g_c2[((size_t)(m * 12 + kt) * 6 + nt) * 32 + l] =
            pack4(s2[k0 * CIN + n], s2[(k0 + 1) * CIN + n],
                  s2[(k0 + 8) * CIN + n], s2[(k0 + 9) * CIN + n]);
    }
}

__global__ void prep_var_frag(const float* __restrict__ w1,
                              const float* __restrict__ w2) {
    int v = blockIdx.x;
    __shared__ float s1[2500], s2[2500];
    {
        const float* a = w1 + (size_t)v * 2500;
        const float* b = w2 + (size_t)v * 2500;
        for (int k = threadIdx.x; k < 2500; k += 128) { s1[k] = a[k]; s2[k] = b[k]; }
    }
    __syncthreads();
    for (int t = threadIdx.x; t < 2 * 13 * 32; t += 128) {
        int kt = t / (13 * 32), nt = (t >> 5) % 13, l = t & 31;
        int k0 = kt * 16 + (l & 3) * 2, n = nt * 8 + (l >> 2);
        auto val = [&](int k) -> float {
            return (k < VIN && n < HV) ? s1[k * HV + n] : 0.f;
        };
        g_v1[((size_t)(v * 2 + kt) * 13 + nt) * 32 + l] =
            pack4(val(k0), val(k0 + 1), val(k0 + 8), val(k0 + 9));
    }
    for (int t = threadIdx.x; t < 7 * 4 * 32; t += 128) {
        int kt = t / (4 * 32), nt = (t >> 5) % 4, l = t & 31;
        int k0 = kt * 16 + (l & 3) * 2, n = nt * 8 + (l >> 2);
        auto val = [&](int k) -> float {
            return (k < HV && n < VIN) ? s2[k * VIN + n] : 0.f;
        };
        g_v2[((size_t)(v * 7 + kt) * 4 + nt) * 32 + l] =
            pack4(val(k0), val(k0 + 1), val(k0 + 8), val(k0 + 9));
    }
}

// ---------------------------------------------------------------------------
// Check kernel: 256 threads, 8 warps; warp owns 16 batch rows (no mt loop).
// B fragments software-pipelined in registers.
// ---------------------------------------------------------------------------
#define PCH 56   // fp16 pitch for chk X staging

__global__ __launch_bounds__(256, 2) void chk_mma(
    const float* __restrict__ b1, const float* __restrict__ b2,
    const int*   __restrict__ v2c)
{
    __shared__ __half Xh[128 * PCH], Xl[128 * PCH];
    __shared__ float sb1[HC], sb2[CIN], ssgn[128];
    __shared__ int   sidx[DCd];

    const int m = blockIdx.x, tid = threadIdx.x;
    const int w = tid >> 5, l = tid & 31;
    const int gr = l >> 2, tg = l & 3;

    {
        int row = tid & 127;
        int c0 = (tid >> 7) * 24;          // two half-warpsets split 48 cols
        const float* xin = g_chk_in + (size_t)m * (CIN * Bb) + row;
        #pragma unroll
        for (int c = c0; c < c0 + 24; c++) {
            float v = xin[c * Bb];
            __half h = __float2half_rn(v);
            Xh[row * PCH + c] = h;
            Xl[row * PCH + c] = __float2half_rn(v - __half2float(h));
        }
        for (int k = tid; k < HC; k += 256) sb1[k] = b1[m * HC + k];
        if (tid < CIN) sb2[tid] = b2[m * CIN + tid];
        if (tid < 128) ssgn[tid] = g_sgn[m * Bb + tid];
        if (tid < DCd) sidx[tid] = v2c[m * DCd + tid];
    }
    __syncthreads();

    const int sub = l >> 3, rin = l & 7;
    const int rowA = w * 16 + (sub & 1) * 8 + rin;
    const int colA = (sub >> 1) * 8;
    const uint32_t aXh = smem_u32(Xh) + (uint32_t)(rowA * PCH + colA) * 2;
    const uint32_t aXl = smem_u32(Xl) + (uint32_t)(rowA * PCH + colA) * 2;

    const uint4* pB1 = g_c1 + (size_t)m * (3 * 24 * 32);
    const uint4* pB2 = g_c2 + (size_t)m * (12 * 6 * 32);

    float D2[6][4];
    #pragma unroll
    for (int nt = 0; nt < 6; nt++)
        #pragma unroll
        for (int q = 0; q < 4; q++) D2[nt][q] = 0.f;

    // preload B1 for hc=0
    uint4 B1b[6];
    #pragma unroll
    for (int kt = 0; kt < 3; kt++)
        #pragma unroll
        for (int j = 0; j < 2; j++)
            B1b[kt * 2 + j] = pB1[(kt * 24 + j) * 32 + l];

    for (int hc = 0; hc < 12; hc++) {
        // early-load B2 for this hc (consumed after GEMM1 + gelu)
        uint4 B2b[6];
        #pragma unroll
        for (int nt2 = 0; nt2 < 6; nt2++)
            B2b[nt2] = pB2[(hc * 6 + nt2) * 32 + l];

        float acc[2][4];
        #pragma unroll
        for (int j = 0; j < 2; j++)
            #pragma unroll
            for (int q = 0; q < 4; q++) acc[j][q] = 0.f;

        #pragma unroll
        for (int kt = 0; kt < 3; kt++) {
            uint32_t Ah[4], Al[4];
            uint32_t off = (uint32_t)(kt * 16) * 2;
            ldsm4(Ah, aXh + off);
            ldsm4(Al, aXl + off);
            #pragma unroll
            for (int j = 0; j < 2; j++) {
                uint4 B = B1b[kt * 2 + j];
                mma16816(acc[j], Ah, B.x, B.y);
                mma16816(acc[j], Al, B.x, B.y);
                mma16816(acc[j], Ah, B.z, B.w);
            }
        }
        // prefetch B1 for hc+1 (covered by gelu + GEMM2)
        if (hc < 11) {
            #pragma unroll
            for (int kt = 0; kt < 3; kt++)
                #pragma unroll
                for (int j = 0; j < 2; j++)
                    B1b[kt * 2 + j] = pB1[(kt * 24 + (hc + 1) * 2 + j) * 32 + l];
        }
        // epilogue: bias + gelu + split -> A2 frags for GEMM2 k-tile hc
        uint32_t A2h[4], A2l[4];
        #pragma unroll
        for (int j = 0; j < 2; j++) {
            int n0 = (hc * 2 + j) * 8 + tg * 2;
            float bx = sb1[n0], by = sb1[n0 + 1];
            float g0 = gelu_fast(acc[j][0] + bx);
            float g1 = gelu_fast(acc[j][1] + by);
            float g2 = gelu_fast(acc[j][2] + bx);
            float g3 = gelu_fast(acc[j][3] + by);
            hl2(g0, g1, A2h[j * 2],     A2l[j * 2]);
            hl2(g2, g3, A2h[j * 2 + 1], A2l[j * 2 + 1]);
        }
        // GEMM2 partial: k-tile hc
        #pragma unroll
        for (int nt2 = 0; nt2 < 6; nt2++) {
            uint4 B = B2b[nt2];
            mma16816(D2[nt2], A2h, B.x, B.y);
            mma16816(D2[nt2], A2l, B.x, B.y);
            mma16816(D2[nt2], A2h, B.z, B.w);
        }
    }

    // final epilogue: y = (D2 + b2) * sgn, scatter to g_var_x
    #pragma unroll
    for (int nt2 = 0; nt2 < 6; nt2++) {
        int e = sidx[nt2];
        int n = e / 3, li = e - n * 3;
        int d = tg * 2;
        float bx = sb2[nt2 * 8 + d], by = sb2[nt2 * 8 + d + 1];
        float* base = g_var_x + (size_t)n * (VIN * Bb) + (li * 8 + d) * Bb;
        int r = w * 16 + gr;
        float s0 = ssgn[r], s1v = ssgn[r + 8];
        base[r]          = (D2[nt2][0] + bx) * s0;
        base[Bb + r]     = (D2[nt2][1] + by) * s0;
        base[r + 8]      = (D2[nt2][2] + bx) * s1v;
        base[Bb + r + 8] = (D2[nt2][3] + by) * s1v;
    }
}

// ---------------------------------------------------------------------------
// Var kernel: 256 threads, 8 warps; warp owns 16 rows; B pipelined.
// ---------------------------------------------------------------------------
#define PV 40    // fp16 pitch for var X staging

__global__ __launch_bounds__(256, 2) void var_mma(
    const float* __restrict__ b1, const float* __restrict__ b2,
    const int*   __restrict__ c2v, float* __restrict__ out_llr)
{
    __shared__ __half Xh[128 * PV], Xl[128 * PV];
    __shared__ float sb1[104], sb2[32];
    __shared__ int   sidx[DVd];

    const int n = blockIdx.x, tid = threadIdx.x;
    const int w = tid >> 5, l = tid & 31;
    const int gr = l >> 2, tg = l & 3;

    {
        int row = tid & 127;
        int c0 = (tid >> 7) * 16;           // split 32 cols in two
        const float* xin = g_var_x + (size_t)n * (VIN * Bb) + row;
        #pragma unroll
        for (int c = c0; c < c0 + 16; c++) {
            float v = (c < VIN) ? xin[c * Bb] : 0.f;
            __half h = __float2half_rn(v);
            Xh[row * PV + c] = h;
            Xl[row * PV + c] = __float2half_rn(v - __half2float(h));
        }
        if (tid < 104) sb1[tid] = (tid < HV) ? b1[n * HV + tid] : 0.f;
        if (tid < 32)  sb2[tid] = (tid < VIN) ? b2[n * VIN + tid] : 0.f;
        if (tid < DVd) sidx[tid] = c2v[n * DVd + tid];
    }
    __syncthreads();

    const int sub = l >> 3, rin = l & 7;
    const int rowA = w * 16 + (sub & 1) * 8 + rin;
    const int colA = (sub >> 1) * 8;
    const uint32_t aXh = smem_u32(Xh) + (uint32_t)(rowA * PV + colA) * 2;
    const uint32_t aXl = smem_u32(Xl) + (uint32_t)(rowA * PV + colA) * 2;

    const uint4* pB1 = g_v1 + (size_t)n * (2 * 13 * 32);
    const uint4* pB2 = g_v2 + (size_t)n * (7 * 4 * 32);

    float D2[4][4];
    #pragma unroll
    for (int nt = 0; nt < 4; nt++)
        #pragma unroll
        for (int q = 0; q < 4; q++) D2[nt][q] = 0.f;

    uint4 B1b[4];
    #pragma unroll
    for (int kt = 0; kt < 2; kt++)
        #pragma unroll
        for (int j = 0; j < 2; j++)
            B1b[kt * 2 + j] = pB1[(kt * 13 + j) * 32 + l];

    for (int hc = 0; hc < 6; hc++) {
        uint4 B2b[4];
        #pragma unroll
        for (int nt2 = 0; nt2 < 4; nt2++)
            B2b[nt2] = pB2[(hc * 4 + nt2) * 32 + l];

        float acc[2][4];
        #pragma unroll
        for (int j = 0; j < 2; j++)
            #pragma unroll
            for (int q = 0; q < 4; q++) acc[j][q] = 0.f;

        #pragma unroll
        for (int kt = 0; kt < 2; kt++) {
            uint32_t Ah[4], Al[4];
            uint32_t off = (uint32_t)(kt * 16) * 2;
            ldsm4(Ah, aXh + off);
            ldsm4(Al, aXl + off);
            #pragma unroll
            for (int j = 0; j < 2; j++) {
                uint4 B = B1b[kt * 2 + j];
                mma16816(acc[j], Ah, B.x, B.y);
                mma16816(acc[j], Al, B.x, B.y);
                mma16816(acc[j], Ah, B.z, B.w);
            }
        }
        // prefetch B1 for next iteration (tail nt=12 when hc==5)
        {
            int nxt = (hc < 5) ? (hc + 1) * 2 : 12;
            #pragma unroll
            for (int kt = 0; kt < 2; kt++)
                #pragma unroll
                for (int j = 0; j < 2; j++) {
                    int ntn = (hc < 5) ? (nxt + j) : 12;   // tail uses nt=12 twice
                    B1b[kt * 2 + j] = pB1[(kt * 13 + ntn) * 32 + l];
                }
        }
        uint32_t A2h[4], A2l[4];
        #pragma unroll
        for (int j = 0; j < 2; j++) {
            int n0 = (hc * 2 + j) * 8 + tg * 2;
            float bx = sb1[n0], by = sb1[n0 + 1];
            float g0 = gelu_fast(acc[j][0] + bx);
            float g1 = gelu_fast(acc[j][1] + by);
            float g2 = gelu_fast(acc[j][2] + bx);
            float g3 = gelu_fast(acc[j][3] + by);
            hl2(g0, g1, A2h[j * 2],     A2l[j * 2]);
            hl2(g2, g3, A2h[j * 2 + 1], A2l[j * 2 + 1]);
        }
        #pragma unroll
        for (int nt2 = 0; nt2 < 4; nt2++) {
            uint4 B = B2b[nt2];
            mma16816(D2[nt2], A2h, B.x, B.y);
            mma16816(D2[nt2], A2l, B.x, B.y);
            mma16816(D2[nt2], A2h, B.z, B.w);
        }
    }
    // tail: GEMM1 n-tile 12 -> GEMM2 k-tile 6 (upper half zero)
    {
        float acc[4];
        #pragma unroll
        for (int q = 0; q < 4; q++) acc[q] = 0.f;
        #pragma unroll
        for (int kt = 0; kt < 2; kt++) {
            uint32_t Ah[4], Al[4];
            uint32_t off = (uint32_t)(kt * 16) * 2;
            ldsm4(Ah, aXh + off);
            ldsm4(Al, aXl + off);
            uint4 B = B1b[kt * 2];       // prefetched nt=12
            mma16816(acc, Ah, B.x, B.y);
            mma16816(acc, Al, B.x, B.y);
            mma16816(acc, Ah, B.z, B.w);
        }
        uint32_t A2h[4], A2l[4];
        {
            int n0 = 96 + tg * 2;
            float bx = sb1[n0], by = sb1[n0 + 1];
            float g0 = gelu_fast(acc[0] + bx);
            float g1 = gelu_fast(acc[1] + by);
            float g2 = gelu_fast(acc[2] + bx);
            float g3 = gelu_fast(acc[3] + by);
            hl2(g0, g1, A2h[0], A2l[0]);
            hl2(g2, g3, A2h[1], A2l[1]);
            A2h[2] = 0; A2h[3] = 0;
            A2l[2] = 0; A2l[3] = 0;
        }
        #pragma unroll
        for (int nt2 = 0; nt2 < 4; nt2++) {
            uint4 B = pB2[(6 * 4 + nt2) * 32 + l];
            mma16816(D2[nt2], A2h, B.x, B.y);
            mma16816(D2[nt2], A2l, B.x, B.y);
            mma16816(D2[nt2], A2h, B.z, B.w);
        }
    }

    // epilogue: messages (cols 0..23) scatter, llr (col 24) -> out
    #pragma unroll
    for (int nt2 = 0; nt2 < 3; nt2++) {
        int e = sidx[nt2];
        int mm = e / 6, s = e - mm * 6;
        int d = tg * 2;
        float bx = sb2[nt2 * 8 + d], by = sb2[nt2 * 8 + d + 1];
        float* base = g_chk_in + (size_t)mm * (CIN * Bb) + (s * 8 + d) * Bb;
        int r = w * 16 + gr;
        base[r]          = D2[nt2][0] + bx;
        base[Bb + r]     = D2[nt2][1] + by;
        base[r + 8]      = D2[nt2][2] + bx;
        base[Bb + r + 8] = D2[nt2][3] + by;
    }
    if (tg == 0) {
        float b24 = sb2[24];
        int r = w * 16 + gr;
        out_llr[(size_t)r * Nv + n]       = D2[3][0] + b24;
        out_llr[(size_t)(r + 8) * Nv + n] = D2[3][2] + b24;
    }
}

// ---------------------------------------------------------------------------
extern "C" void kernel_launch(void* const* d_in, const int* in_sizes, int n_in,
                              void* d_out, int out_size)
{
    const int*   synd     = (const int*)  d_in[0];
    const float* prior    = (const float*)d_in[1];
    const float* cw1      = (const float*)d_in[2];
    const float* cb1      = (const float*)d_in[3];
    const float* cw2      = (const float*)d_in[4];
    const float* cb2      = (const float*)d_in[5];
    const float* vw1      = (const float*)d_in[6];
    const float* vb1      = (const float*)d_in[7];
    const float* vw2      = (const float*)d_in[8];
    const float* vb2      = (const float*)d_in[9];
    const int*   chk_nbrs = (const int*)  d_in[10];
    const int*   c2v      = (const int*)  d_in[11];
    const int*   v2c      = (const int*)  d_in[12];
    float* out = (float*)d_out;

    cudaFuncSetAttribute(prep_chk_frag, cudaFuncAttributeMaxDynamicSharedMemorySize, 73728);

    prep_chk_frag<<<Mm, 256, 73728>>>(cw1, cw2);
    prep_var_frag<<<Nv, 128>>>(vw1, vw2);
    init_chk<<<(Mm * CIN * Bb + 255) / 256, 256>>>(prior, chk_nbrs);
    init_var<<<(Nv * Bb + 255) / 256, 256>>>(prior);
    init_sgn<<<(Mm * Bb + 255) / 256, 256>>>(synd);

    for (int t = 0; t < Tt; t++) {
        chk_mma<<<Mm, 256>>>(cb1, cb2, v2c);
        var_mma<<<Nv, 256>>>(vb1, vb2, c2v, out + (size_t)t * Bb * Nv);
    }
}

// round 16
// speedup vs baseline: 1.1692x; 1.1692x over previous
#include <cuda_runtime.h>
#include <cuda_fp16.h>
#include <cstdint>

// Problem constants
#define Mm   1024
#define Nv   2048
#define DVd  3
#define DCd  6
#define Bb   128
#define Tt   5
#define CIN  48
#define VIN  25
#define HC   192
#define HV   100

// ---------------------------------------------------------------------------
// Device-global scratch
// ---------------------------------------------------------------------------
__device__ float g_chk_in[Mm * CIN * Bb];   // [m][c][b]
__device__ float g_var_x [Nv * VIN * Bb];   // [n][c][b], c=24 -> prior
__device__ float g_sgn   [Mm * Bb];         // [m][b] syndrome signs

// Fragment-packed fp16 weights, hi+lo fused per uint4 {bh0,bh1,bl0,bl1}.
// index: ((group*KT + kt)*NT + nt)*32 + lane
__device__ uint4 g_c1[Mm * 3 * 24 * 32];    // chk W1 48x192
__device__ uint4 g_c2[Mm * 12 * 6 * 32];    // chk W2 192x48
__device__ uint4 g_v1[Nv * 2 * 13 * 32];    // var W1 32x104 (padded)
__device__ uint4 g_v2[Nv * 7 * 4  * 32];    // var W2 112x32 (padded)

// Fast gelu: Phi via A&S 7.1.26 erf approx (|err| <= 1.5e-7), ~14 ops.
__device__ __forceinline__ float gelu_fast(float v) {
    float z = 0.70710678118654752f * v;
    float a = fabsf(z);
    float t = __fdividef(1.0f, fmaf(0.3275911f, a, 1.0f));
    float p = fmaf(1.061405429f, t, -1.453152027f);
    p = fmaf(p, t, 1.421413741f);
    p = fmaf(p, t, -0.284496736f);
    p = fmaf(p, t, 0.254829592f);
    p = p * t;
    float e = __expf(-a * a);
    float erf_a = fmaf(-p, e, 1.0f);
    float ph = (z >= 0.f) ? fmaf(0.5f, erf_a, 0.5f)
                          : fmaf(-0.5f, erf_a, 0.5f);
    return v * ph;
}

__device__ __forceinline__ uint32_t smem_u32(const void* p) {
    uint32_t a;
    asm("{ .reg .u64 t; cvta.to.shared.u64 t, %1; cvt.u32.u64 %0, t; }" : "=r"(a) : "l"(p));
    return a;
}

// pack two floats into fp16x2 (lo -> low half)
__device__ __forceinline__ uint32_t pkh(float lo, float hi) {
    __half2 h = __floats2half2_rn(lo, hi);
    return *reinterpret_cast<uint32_t*>(&h);
}
__device__ __forceinline__ void hl2(float a, float b, uint32_t& H, uint32_t& L) {
    float ra = __half2float(__float2half_rn(a));
    float rb = __half2float(__float2half_rn(b));
    H = pkh(a, b);
    L = pkh(a - ra, b - rb);
}

// D += A * B  (m16n8k16 fp16->fp32)
__device__ __forceinline__ void mma16816(float* c, const uint32_t* a,
                                         uint32_t b0, uint32_t b1) {
    asm volatile(
        "mma.sync.aligned.m16n8k16.row.col.f32.f16.f16.f32 "
        "{%0,%1,%2,%3}, {%4,%5,%6,%7}, {%8,%9}, {%0,%1,%2,%3};"
        : "+f"(c[0]), "+f"(c[1]), "+f"(c[2]), "+f"(c[3])
        : "r"(a[0]), "r"(a[1]), "r"(a[2]), "r"(a[3]), "r"(b0), "r"(b1));
}
__device__ __forceinline__ void ldsm4(uint32_t* r, uint32_t saddr) {
    asm volatile("ldmatrix.sync.aligned.m8n8.x4.shared.b16 {%0,%1,%2,%3}, [%4];"
        : "=r"(r[0]), "=r"(r[1]), "=r"(r[2]), "=r"(r[3]) : "r"(saddr));
}
__device__ __forceinline__ void cpa16(uint32_t saddr, const void* g) {
    asm volatile("cp.async.cg.shared.global [%0], [%1], 16;"
                 :: "r"(saddr), "l"(g));
}
#define CPA_COMMIT() asm volatile("cp.async.commit_group;" ::: "memory")
#define CPA_WAIT0()  asm volatile("cp.async.wait_group 0;" ::: "memory")

// ---------------------------------------------------------------------------
// Init kernels
// ---------------------------------------------------------------------------
__global__ void init_chk(const float* __restrict__ prior,
                         const int*   __restrict__ chk_nbrs) {
    int i = blockIdx.x * 256 + threadIdx.x;
    if (i >= Mm * CIN * Bb) return;
    int c = (i >> 7) % CIN;
    float v = 0.0f;
    if ((c & 7) == 0) {
        int m = i / (CIN * Bb);
        v = prior[chk_nbrs[m * DCd + (c >> 3)]];
    }
    g_chk_in[i] = v;
}
__global__ void init_var(const float* __restrict__ prior) {
    int i = blockIdx.x * 256 + threadIdx.x;
    if (i >= Nv * Bb) return;
    int n = i >> 7, b = i & 127;
    g_var_x[(size_t)n * (VIN * Bb) + 24 * Bb + b] = prior[n];
}
__global__ void init_sgn(const int* __restrict__ synd) {
    int i = blockIdx.x * 256 + threadIdx.x;      // m*128 + b
    if (i >= Mm * Bb) return;
    int mi = i >> 7, b = i & 127;
    g_sgn[i] = 1.0f - 2.0f * (float)synd[b * Mm + mi];
}

// ---------------------------------------------------------------------------
// Prep kernels: pack weights into mma B-fragment order, fp16 hi/lo fused.
// B frag (kt,nt,lane): k0 = kt*16 + (l%4)*2, n = nt*8 + l/4
//   b0 = {B[k0][n], B[k0+1][n]},  b1 = {B[k0+8][n], B[k0+9][n]}
// ---------------------------------------------------------------------------
__device__ __forceinline__ uint4 pack4(float v0, float v1, float v2, float v3) {
    uint32_t h0, l0, h1, l1;
    hl2(v0, v1, h0, l0);
    hl2(v2, v3, h1, l1);
    return make_uint4(h0, h1, l0, l1);
}

__global__ void prep_chk_frag(const float* __restrict__ w1,
                              const float* __restrict__ w2) {
    int m = blockIdx.x;
    extern __shared__ float ps[];            // 9216 + 9216
    float* s1 = ps;
    float* s2 = ps + 9216;
    {
        const float4* a = (const float4*)(w1 + (size_t)m * 9216);
        const float4* b = (const float4*)(w2 + (size_t)m * 9216);
        float4* d1 = (float4*)s1;
        float4* d2 = (float4*)s2;
        for (int k = threadIdx.x; k < 2304; k += 256) { d1[k] = a[k]; d2[k] = b[k]; }
    }
    __syncthreads();
    for (int t = threadIdx.x; t < 3 * 24 * 32; t += 256) {
        int kt = t / (24 * 32), nt = (t >> 5) % 24, l = t & 31;
        int k0 = kt * 16 + (l & 3) * 2, n = nt * 8 + (l >> 2);
        g_c1[((size_t)(m * 3 + kt) * 24 + nt) * 32 + l] =
            pack4(s1[k0 * HC + n], s1[(k0 + 1) * HC + n],
                  s1[(k0 + 8) * HC + n], s1[(k0 + 9) * HC + n]);
    }
    for (int t = threadIdx.x; t < 12 * 6 * 32; t += 256) {
        int kt = t / (6 * 32), nt = (t >> 5) % 6, l = t & 31;
        int k0 = kt * 16 + (l & 3) * 2, n = nt * 8 + (l >> 2);
        g_c2[((size_t)(m * 12 + kt) * 6 + nt) * 32 + l] =
            pack4(s2[k0 * CIN + n], s2[(k0 + 1) * CIN + n],
                  s2[(k0 + 8) * CIN + n], s2[(k0 + 9) * CIN + n]);
    }
}

__global__ void prep_var_frag(const float* __restrict__ w1,
                              const float* __restrict__ w2) {
    int v = blockIdx.x;
    __shared__ float s1[2500], s2[2500];
    {
        const float* a = w1 + (size_t)v * 2500;
        const float* b = w2 + (size_t)v * 2500;
        for (int k = threadIdx.x; k < 2500; k += 128) { s1[k] = a[k]; s2[k] = b[k]; }
    }
    __syncthreads();
    for (int t = threadIdx.x; t < 2 * 13 * 32; t += 128) {
        int kt = t / (13 * 32), nt = (t >> 5) % 13, l = t & 31;
        int k0 = kt * 16 + (l & 3) * 2, n = nt * 8 + (l >> 2);
        auto val = [&](int k) -> float {
            return (k < VIN && n < HV) ? s1[k * HV + n] : 0.f;
        };
        g_v1[((size_t)(v * 2 + kt) * 13 + nt) * 32 + l] =
            pack4(val(k0), val(k0 + 1), val(k0 + 8), val(k0 + 9));
    }
    for (int t = threadIdx.x; t < 7 * 4 * 32; t += 128) {
        int kt = t / (4 * 32), nt = (t >> 5) % 4, l = t & 31;
        int k0 = kt * 16 + (l & 3) * 2, n = nt * 8 + (l >> 2);
        auto val = [&](int k) -> float {
            return (k < HV && n < VIN) ? s2[k * VIN + n] : 0.f;
        };
        g_v2[((size_t)(v * 7 + kt) * 4 + nt) * 32 + l] =
            pack4(val(k0), val(k0 + 1), val(k0 + 8), val(k0 + 9));
    }
}

// ---------------------------------------------------------------------------
// Check kernel: R13 structure (128 thr, 4 warps, mt=2, occ 4) +
// cp.async double-buffered smem staging of B fragments (1 copy/CTA, not 4).
// ---------------------------------------------------------------------------
#define PCH 56   // fp16 pitch for chk X staging

__global__ __launch_bounds__(128, 4) void chk_mma(
    const float* __restrict__ b1, const float* __restrict__ b2,
    const int*   __restrict__ v2c)
{
    __shared__ __half Xh[128 * PCH], Xl[128 * PCH];
    __shared__ uint4  sB[2][12 * 32];        // [buf][frag*32 + lane]
    __shared__ float sb1[HC], sb2[CIN], ssgn[128];
    __shared__ int   sidx[DCd];

    const int m = blockIdx.x, tid = threadIdx.x;
    const int w = tid >> 5, l = tid & 31;
    const int gr = l >> 2, tg = l & 3;

    const uint4* pB1 = g_c1 + (size_t)m * (3 * 24 * 32);
    const uint4* pB2 = g_c2 + (size_t)m * (12 * 6 * 32);
    const uint32_t sBa[2] = { smem_u32(&sB[0][0]), smem_u32(&sB[1][0]) };

    // stage B for hc: frags 0..5 = B1(kt=f>>1, j=f&1), 6..11 = B2(nt2=f-6)
    auto stage = [&](int buf, int hc) {
        #pragma unroll
        for (int i = 0; i < 3; i++) {
            int idx = i * 128 + tid;
            int f = idx >> 5, ll = idx & 31;
            const uint4* g = (f < 6)
                ? &pB1[(((f >> 1) * 24) + hc * 2 + (f & 1)) * 32 + ll]
                : &pB2[((hc * 6) + (f - 6)) * 32 + ll];
            cpa16(sBa[buf] + (uint32_t)idx * 16, g);
        }
        CPA_COMMIT();
    };

    stage(0, 0);                               // prologue prefetch

    {
        const float* xin = g_chk_in + (size_t)m * (CIN * Bb) + tid;
        #pragma unroll 8
        for (int c = 0; c < CIN; c++) {
            float v = xin[c * Bb];
            __half h = __float2half_rn(v);
            Xh[tid * PCH + c] = h;
            Xl[tid * PCH + c] = __float2half_rn(v - __half2float(h));
        }
        for (int k = tid; k < HC; k += 128) sb1[k] = b1[m * HC + k];
        if (tid < CIN) sb2[tid] = b2[m * CIN + tid];
        ssgn[tid] = g_sgn[m * Bb + tid];
        if (tid < DCd) sidx[tid] = v2c[m * DCd + tid];
    }

    const int sub = l >> 3, rin = l & 7;
    const int rowA = w * 32 + (sub & 1) * 8 + rin;
    const int colA = (sub >> 1) * 8;
    const uint32_t aXh = smem_u32(Xh) + (uint32_t)(rowA * PCH + colA) * 2;
    const uint32_t aXl = smem_u32(Xl) + (uint32_t)(rowA * PCH + colA) * 2;

    float D2[2][6][4];
    #pragma unroll
    for (int mt = 0; mt < 2; mt++)
        #pragma unroll
        for (int nt = 0; nt < 6; nt++)
            #pragma unroll
            for (int q = 0; q < 4; q++) D2[mt][nt][q] = 0.f;

    for (int hc = 0; hc < 12; hc++) {
        const int buf = hc & 1;
        CPA_WAIT0();                 // stage(hc) complete
        __syncthreads();             // data visible; prev compute done reading buf^1
        if (hc + 1 < 12) stage(buf ^ 1, hc + 1);   // overlap with compute

        const uint4* sB1 = &sB[buf][0];
        const uint4* sB2 = &sB[buf][6 * 32];

        float acc[2][2][4];
        #pragma unroll
        for (int mt = 0; mt < 2; mt++)
            #pragma unroll
            for (int j = 0; j < 2; j++)
                #pragma unroll
                for (int q = 0; q < 4; q++) acc[mt][j][q] = 0.f;

        #pragma unroll
        for (int kt = 0; kt < 3; kt++) {
            uint32_t Ah[2][4], Al[2][4];
            #pragma unroll
            for (int mt = 0; mt < 2; mt++) {
                uint32_t off = (uint32_t)(mt * 16 * PCH + kt * 16) * 2;
                ldsm4(Ah[mt], aXh + off);
                ldsm4(Al[mt], aXl + off);
            }
            #pragma unroll
            for (int j = 0; j < 2; j++) {
                uint4 B = sB1[(kt * 2 + j) * 32 + l];
                #pragma unroll
                for (int mt = 0; mt < 2; mt++) {
                    mma16816(acc[mt][j], Ah[mt], B.x, B.y);
                    mma16816(acc[mt][j], Al[mt], B.x, B.y);
                    mma16816(acc[mt][j], Ah[mt], B.z, B.w);
                }
            }
        }
        // epilogue: bias + gelu + split -> A2 frags for GEMM2 k-tile hc
        uint32_t A2h[2][4], A2l[2][4];
        #pragma unroll
        for (int j = 0; j < 2; j++) {
            int n0 = (hc * 2 + j) * 8 + tg * 2;
            float bx = sb1[n0], by = sb1[n0 + 1];
            #pragma unroll
            for (int mt = 0; mt < 2; mt++) {
                float g0 = gelu_fast(acc[mt][j][0] + bx);
                float g1 = gelu_fast(acc[mt][j][1] + by);
                float g2 = gelu_fast(acc[mt][j][2] + bx);
                float g3 = gelu_fast(acc[mt][j][3] + by);
                hl2(g0, g1, A2h[mt][j * 2],     A2l[mt][j * 2]);
                hl2(g2, g3, A2h[mt][j * 2 + 1], A2l[mt][j * 2 + 1]);
            }
        }
        // GEMM2 partial: k-tile hc
        #pragma unroll
        for (int nt2 = 0; nt2 < 6; nt2++) {
            uint4 B = sB2[nt2 * 32 + l];
            #pragma unroll
            for (int mt = 0; mt < 2; mt++) {
                mma16816(D2[mt][nt2], A2h[mt], B.x, B.y);
                mma16816(D2[mt][nt2], A2l[mt], B.x, B.y);
                mma16816(D2[mt][nt2], A2h[mt], B.z, B.w);
            }
        }
    }

    // final epilogue: y = (D2 + b2) * sgn, scatter to g_var_x
    #pragma unroll
    for (int nt2 = 0; nt2 < 6; nt2++) {
        int e = sidx[nt2];
        int n = e / 3, li = e - n * 3;
        int d = tg * 2;
        float bx = sb2[nt2 * 8 + d], by = sb2[nt2 * 8 + d + 1];
        float* base = g_var_x + (size_t)n * (VIN * Bb) + (li * 8 + d) * Bb;
        #pragma unroll
        for (int mt = 0; mt < 2; mt++) {
            int r = w * 32 + mt * 16 + gr;
            float s0 = ssgn[r], s1v = ssgn[r + 8];
            base[r]          = (D2[mt][nt2][0] + bx) * s0;
            base[Bb + r]     = (D2[mt][nt2][1] + by) * s0;
            base[r + 8]      = (D2[mt][nt2][2] + bx) * s1v;
            base[Bb + r + 8] = (D2[mt][nt2][3] + by) * s1v;
        }
    }
}

// ---------------------------------------------------------------------------
// Var kernel: R13 structure + cp.async double-buffered B staging.
// 7 pipeline stages (6 main half-chunks + tail).
// ---------------------------------------------------------------------------
#define PV 40    // fp16 pitch for var X staging

__global__ __launch_bounds__(128, 4) void var_mma(
    const float* __restrict__ b1, const float* __restrict__ b2,
    const int*   __restrict__ c2v, float* __restrict__ out_llr)
{
    __shared__ __half Xh[128 * PV], Xl[128 * PV];
    __shared__ uint4  sB[2][8 * 32];
    __shared__ float sb1[104], sb2[32];
    __shared__ int   sidx[DVd];

    const int n = blockIdx.x, tid = threadIdx.x;
    const int w = tid >> 5, l = tid & 31;
    const int gr = l >> 2, tg = l & 3;

    const uint4* pB1 = g_v1 + (size_t)n * (2 * 13 * 32);
    const uint4* pB2 = g_v2 + (size_t)n * (7 * 4 * 32);
    const uint32_t sBa[2] = { smem_u32(&sB[0][0]), smem_u32(&sB[1][0]) };

    // stage hc (0..6): frags 0..3 = B1(kt=f>>1, nt = hc<6 ? hc*2+(f&1) : 12),
    //                  frags 4..7 = B2(hc*4 + f-4)
    auto stage = [&](int buf, int hc) {
        #pragma unroll
        for (int i = 0; i < 2; i++) {
            int idx = i * 128 + tid;
            int f = idx >> 5, ll = idx & 31;
            const uint4* g;
            if (f < 4) {
                int nt = (hc < 6) ? hc * 2 + (f & 1) : 12;
                g = &pB1[(((f >> 1) * 13) + nt) * 32 + ll];
            } else {
                g = &pB2[((hc * 4) + (f - 4)) * 32 + ll];
            }
            cpa16(sBa[buf] + (uint32_t)idx * 16, g);
        }
        CPA_COMMIT();
    };

    stage(0, 0);

    {
        const float* xin = g_var_x + (size_t)n * (VIN * Bb) + tid;
        #pragma unroll 8
        for (int c = 0; c < 32; c++) {
            float v = (c < VIN) ? xin[c * Bb] : 0.f;
            __half h = __float2half_rn(v);
            Xh[tid * PV + c] = h;
            Xl[tid * PV + c] = __float2half_rn(v - __half2float(h));
        }
        if (tid < 104) sb1[tid] = (tid < HV) ? b1[n * HV + tid] : 0.f;
        if (tid < 32)  sb2[tid] = (tid < VIN) ? b2[n * VIN + tid] : 0.f;
        if (tid < DVd) sidx[tid] = c2v[n * DVd + tid];
    }

    const int sub = l >> 3, rin = l & 7;
    const int rowA = w * 32 + (sub & 1) * 8 + rin;
    const int colA = (sub >> 1) * 8;
    const uint32_t aXh = smem_u32(Xh) + (uint32_t)(rowA * PV + colA) * 2;
    const uint32_t aXl = smem_u32(Xl) + (uint32_t)(rowA * PV + colA) * 2;

    float D2[2][4][4];
    #pragma unroll
    for (int mt = 0; mt < 2; mt++)
        #pragma unroll
        for (int nt = 0; nt < 4; nt++)
            #pragma unroll
            for (int q = 0; q < 4; q++) D2[mt][nt][q] = 0.f;

    for (int hc = 0; hc < 7; hc++) {
        const int buf = hc & 1;
        CPA_WAIT0();
        __syncthreads();
        if (hc + 1 < 7) stage(buf ^ 1, hc + 1);

        const uint4* sB1 = &sB[buf][0];
        const uint4* sB2 = &sB[buf][4 * 32];

        if (hc < 6) {
            float acc[2][2][4];
            #pragma unroll
            for (int mt = 0; mt < 2; mt++)
                #pragma unroll
                for (int j = 0; j < 2; j++)
                    #pragma unroll
                    for (int q = 0; q < 4; q++) acc[mt][j][q] = 0.f;

            #pragma unroll
            for (int kt = 0; kt < 2; kt++) {
                uint32_t Ah[2][4], Al[2][4];
                #pragma unroll
                for (int mt = 0; mt < 2; mt++) {
                    uint32_t off = (uint32_t)(mt * 16 * PV + kt * 16) * 2;
                    ldsm4(Ah[mt], aXh + off);
                    ldsm4(Al[mt], aXl + off);
                }
                #pragma unroll
                for (int j = 0; j < 2; j++) {
                    uint4 B = sB1[(kt * 2 + j) * 32 + l];
                    #pragma unroll
                    for (int mt = 0; mt < 2; mt++) {
                        mma16816(acc[mt][j], Ah[mt], B.x, B.y);
                        mma16816(acc[mt][j], Al[mt], B.x, B.y);
                        mma16816(acc[mt][j], Ah[mt], B.z, B.w);
                    }
                }
            }
            uint32_t A2h[2][4], A2l[2][4];
            #pragma unroll
            for (int j = 0; j < 2; j++) {
                int n0 = (hc * 2 + j) * 8 + tg * 2;
                float bx = sb1[n0], by = sb1[n0 + 1];
                #pragma unroll
                for (int mt = 0; mt < 2; mt++) {
                    float g0 = gelu_fast(acc[mt][j][0] + bx);
                    float g1 = gelu_fast(acc[mt][j][1] + by);
                    float g2 = gelu_fast(acc[mt][j][2] + bx);
                    float g3 = gelu_fast(acc[mt][j][3] + by);
                    hl2(g0, g1, A2h[mt][j * 2],     A2l[mt][j * 2]);
                    hl2(g2, g3, A2h[mt][j * 2 + 1], A2l[mt][j * 2 + 1]);
                }
            }
            #pragma unroll
            for (int nt2 = 0; nt2 < 4; nt2++) {
                uint4 B = sB2[nt2 * 32 + l];
                #pragma unroll
                for (int mt = 0; mt < 2; mt++) {
                    mma16816(D2[mt][nt2], A2h[mt], B.x, B.y);
                    mma16816(D2[mt][nt2], A2l[mt], B.x, B.y);
                    mma16816(D2[mt][nt2], A2h[mt], B.z, B.w);
                }
            }
        } else {
            // tail: GEMM1 n-tile 12 -> GEMM2 k-tile 6 (upper half zero)
            float acc[2][4];
            #pragma unroll
            for (int mt = 0; mt < 2; mt++)
                #pragma unroll
                for (int q = 0; q < 4; q++) acc[mt][q] = 0.f;
            #pragma unroll
            for (int kt = 0; kt < 2; kt++) {
                uint32_t Ah[2][4], Al[2][4];
                #pragma unroll
                for (int mt = 0; mt < 2; mt++) {
                    uint32_t off = (uint32_t)(mt * 16 * PV + kt * 16) * 2;
                    ldsm4(Ah[mt], aXh + off);
                    ldsm4(Al[mt], aXl + off);
                }
                uint4 B = sB1[(kt * 2) * 32 + l];    // nt=12 frag
                #pragma unroll
                for (int mt = 0; mt < 2; mt++) {
                    mma16816(acc[mt], Ah[mt], B.x, B.y);
                    mma16816(acc[mt], Al[mt], B.x, B.y);
                    mma16816(acc[mt], Ah[mt], B.z, B.w);
                }
            }
            uint32_t A2h[2][4], A2l[2][4];
            {
                int n0 = 96 + tg * 2;
                float bx = sb1[n0], by = sb1[n0 + 1];
                #pragma unroll
                for (int mt = 0; mt < 2; mt++) {
                    float g0 = gelu_fast(acc[mt][0] + bx);
                    float g1 = gelu_fast(acc[mt][1] + by);
                    float g2 = gelu_fast(acc[mt][2] + bx);
                    float g3 = gelu_fast(acc[mt][3] + by);
                    hl2(g0, g1, A2h[mt][0], A2l[mt][0]);
                    hl2(g2, g3, A2h[mt][1], A2l[mt][1]);
                    A2h[mt][2] = 0; A2h[mt][3] = 0;
                    A2l[mt][2] = 0; A2l[mt][3] = 0;
                }
            }
            #pragma unroll
            for (int nt2 = 0; nt2 < 4; nt2++) {
                uint4 B = sB2[nt2 * 32 + l];
                #pragma unroll
                for (int mt = 0; mt < 2; mt++) {
                    mma16816(D2[mt][nt2], A2h[mt], B.x, B.y);
                    mma16816(D2[mt][nt2], A2l[mt], B.x, B.y);
                    mma16816(D2[mt][nt2], A2h[mt], B.z, B.w);
                }
            }
        }
    }

    // epilogue: messages (cols 0..23) scatter, llr (col 24) -> out
    #pragma unroll
    for (int nt2 = 0; nt2 < 3; nt2++) {
        int e = sidx[nt2];
        int mm = e / 6, s = e - mm * 6;
        int d = tg * 2;
        float bx = sb2[nt2 * 8 + d], by = sb2[nt2 * 8 + d + 1];
        float* base = g_chk_in + (size_t)mm * (CIN * Bb) + (s * 8 + d) * Bb;
        #pragma unroll
        for (int mt = 0; mt < 2; mt++) {
            int r = w * 32 + mt * 16 + gr;
            base[r]          = D2[mt][nt2][0] + bx;
            base[Bb + r]     = D2[mt][nt2][1] + by;
            base[r + 8]      = D2[mt][nt2][2] + bx;
            base[Bb + r + 8] = D2[mt][nt2][3] + by;
        }
    }
    if (tg == 0) {
        float b24 = sb2[24];
        #pragma unroll
        for (int mt = 0; mt < 2; mt++) {
            int r = w * 32 + mt * 16 + gr;
            out_llr[(size_t)r * Nv + n]       = D2[mt][3][0] + b24;
            out_llr[(size_t)(r + 8) * Nv + n] = D2[mt][3][2] + b24;
        }
    }
}

// ---------------------------------------------------------------------------
extern "C" void kernel_launch(void* const* d_in, const int* in_sizes, int n_in,
                              void* d_out, int out_size)
{
    const int*   synd     = (const int*)  d_in[0];
    const float* prior    = (const float*)d_in[1];
    const float* cw1      = (const float*)d_in[2];
    const float* cb1      = (const float*)d_in[3];
    const float* cw2      = (const float*)d_in[4];
    const float* cb2      = (const float*)d_in[5];
    const float* vw1      = (const float*)d_in[6];
    const float* vb1      = (const float*)d_in[7];
    const float* vw2      = (const float*)d_in[8];
    const float* vb2      = (const float*)d_in[9];
    const int*   chk_nbrs = (const int*)  d_in[10];
    const int*   c2v      = (const int*)  d_in[11];
    const int*   v2c      = (const int*)  d_in[12];
    float* out = (float*)d_out;

    cudaFuncSetAttribute(prep_chk_frag, cudaFuncAttributeMaxDynamicSharedMemorySize, 73728);

    prep_chk_frag<<<Mm, 256, 73728>>>(cw1, cw2);
    prep_var_frag<<<Nv, 128>>>(vw1, vw2);
    init_chk<<<(Mm * CIN * Bb + 255) / 256, 256>>>(prior, chk_nbrs);
    init_var<<<(Nv * Bb + 255) / 256, 256>>>(prior);
    init_sgn<<<(Mm * Bb + 255) / 256, 256>>>(synd);

    for (int t = 0; t < Tt; t++) {
        chk_mma<<<Mm, 128>>>(cb1, cb2, v2c);
        var_mma<<<Nv, 128>>>(vb1, vb2, c2v, out + (size_t)t * Bb * Nv);
    }
}